// round 15
// baseline (speedup 1.0000x reference)
#include <cuda_runtime.h>
#include <cstdint>

// Fixed shapes: pooled/indices [4,64,32,32,32], out [4,64,64,64,64]
#define NCHAN 256
#define POOL_PER_CHAN 32768
#define SLOTS 8
#define S_TOTAL 262144.0f

__device__ float d_partial[NCHAN * SLOTS];

// ---------------------------------------------------------------------------
// Kernel 1 (primary): partial sum(silu(pooled)), 2048 blocks x 256 thr.
// Two 256-bit loads per thread, front-batched. PLC trigger at entry.
// (Unchanged from the proven 59.5us version.)
// ---------------------------------------------------------------------------
__global__ __launch_bounds__(256) void gating_partial(const float* __restrict__ pooled) {
    cudaTriggerProgrammaticLaunchCompletion();

    const float* p = pooled + (size_t)blockIdx.x * 4096 + threadIdx.x * 8;

    float v0, v1, v2, v3, v4, v5, v6, v7;
    float w0, w1, w2, w3, w4, w5, w6, w7;
    asm volatile("ld.global.nc.v8.f32 {%0,%1,%2,%3,%4,%5,%6,%7}, [%8];"
                 : "=f"(v0), "=f"(v1), "=f"(v2), "=f"(v3),
                   "=f"(v4), "=f"(v5), "=f"(v6), "=f"(v7)
                 : "l"(p));
    asm volatile("ld.global.nc.v8.f32 {%0,%1,%2,%3,%4,%5,%6,%7}, [%8];"
                 : "=f"(w0), "=f"(w1), "=f"(w2), "=f"(w3),
                   "=f"(w4), "=f"(w5), "=f"(w6), "=f"(w7)
                 : "l"(p + 2048));

    float s = 0.0f;
    s += v0 * (1.0f / (1.0f + __expf(-v0)));
    s += v1 * (1.0f / (1.0f + __expf(-v1)));
    s += v2 * (1.0f / (1.0f + __expf(-v2)));
    s += v3 * (1.0f / (1.0f + __expf(-v3)));
    s += v4 * (1.0f / (1.0f + __expf(-v4)));
    s += v5 * (1.0f / (1.0f + __expf(-v5)));
    s += v6 * (1.0f / (1.0f + __expf(-v6)));
    s += v7 * (1.0f / (1.0f + __expf(-v7)));
    s += w0 * (1.0f / (1.0f + __expf(-w0)));
    s += w1 * (1.0f / (1.0f + __expf(-w1)));
    s += w2 * (1.0f / (1.0f + __expf(-w2)));
    s += w3 * (1.0f / (1.0f + __expf(-w3)));
    s += w4 * (1.0f / (1.0f + __expf(-w4)));
    s += w5 * (1.0f / (1.0f + __expf(-w5)));
    s += w6 * (1.0f / (1.0f + __expf(-w6)));
    s += w7 * (1.0f / (1.0f + __expf(-w7)));

    #pragma unroll
    for (int off = 16; off > 0; off >>= 1)
        s += __shfl_xor_sync(0xFFFFFFFFu, s, off);

    __shared__ float sh[8];
    const int lane = threadIdx.x & 31;
    const int wid  = threadIdx.x >> 5;
    if (lane == 0) sh[wid] = s;
    __syncthreads();
    if (threadIdx.x == 0) {
        float t = sh[0];
        #pragma unroll
        for (int j = 1; j < 8; j++) t += sh[j];
        d_partial[blockIdx.x] = t;     // slot = bc*8 + sub (fixed, deterministic)
    }
}

// ---------------------------------------------------------------------------
// Kernel 2 (PSS secondary): dense unpool + gate. NOW 32 outputs/thread
// (16 pooling windows): 4x256-bit front-issued loads, 4x256-bit stores.
// u (32-output index) layout: [bc(8) | d0(6) | ho(6) | wo32(1)]
// ---------------------------------------------------------------------------
__global__ __launch_bounds__(256) void unpool_kernel(const float* __restrict__ pooled,
                                                     const int*   __restrict__ indices,
                                                     float*       __restrict__ out) {
    const unsigned bc = blockIdx.x >> 5;           // 32 blocks per channel

    const unsigned u  = blockIdx.x * 256u + threadIdx.x;   // 0 .. 2097151
    const unsigned wo = (u & 1u) << 5;             // 0 or 32
    const unsigned ho = (u >> 1) & 63u;
    const unsigned d0 = (u >> 7) & 63u;

    const unsigned pbase = bc * POOL_PER_CHAN + (d0 >> 1) * 1024u + (ho >> 1) * 32u + (wo >> 1);

    // Front-issue all four 256-bit loads (MLP=4, independent of gating grid).
    float fa0, fa1, fa2, fa3, fa4, fa5, fa6, fa7;  // idx bits [0..7]
    float fb0, fb1, fb2, fb3, fb4, fb5, fb6, fb7;  // idx bits [8..15]
    float pa0, pa1, pa2, pa3, pa4, pa5, pa6, pa7;  // pooled   [0..7]
    float pb0, pb1, pb2, pb3, pb4, pb5, pb6, pb7;  // pooled   [8..15]
    asm volatile("ld.global.nc.v8.f32 {%0,%1,%2,%3,%4,%5,%6,%7}, [%8];"
                 : "=f"(fa0), "=f"(fa1), "=f"(fa2), "=f"(fa3),
                   "=f"(fa4), "=f"(fa5), "=f"(fa6), "=f"(fa7)
                 : "l"(reinterpret_cast<const float*>(indices + pbase)));
    asm volatile("ld.global.nc.v8.f32 {%0,%1,%2,%3,%4,%5,%6,%7}, [%8];"
                 : "=f"(fb0), "=f"(fb1), "=f"(fb2), "=f"(fb3),
                   "=f"(fb4), "=f"(fb5), "=f"(fb6), "=f"(fb7)
                 : "l"(reinterpret_cast<const float*>(indices + pbase + 8)));
    asm volatile("ld.global.nc.v8.f32 {%0,%1,%2,%3,%4,%5,%6,%7}, [%8];"
                 : "=f"(pa0), "=f"(pa1), "=f"(pa2), "=f"(pa3),
                   "=f"(pa4), "=f"(pa5), "=f"(pa6), "=f"(pa7)
                 : "l"(pooled + pbase));
    asm volatile("ld.global.nc.v8.f32 {%0,%1,%2,%3,%4,%5,%6,%7}, [%8];"
                 : "=f"(pb0), "=f"(pb1), "=f"(pb2), "=f"(pb3),
                   "=f"(pb4), "=f"(pb5), "=f"(pb6), "=f"(pb7)
                 : "l"(pooled + pbase + 8));

    // Wait for gating grid completion (PDL dependency point).
    cudaGridDependencySynchronize();

    __shared__ float gsh;
    if (threadIdx.x == 0) {
        const float* pp = d_partial + bc * SLOTS;
        float t = 0.0f;
        #pragma unroll
        for (int j = 0; j < SLOTS; j++) t += pp[j];   // fixed order: deterministic
        float m = t / S_TOTAL;
        gsh = fminf(m, 0.0f) - log1pf(__expf(-fabsf(m)));   // log_sigmoid(m)
    }
    __syncthreads();
    const float g = gsh;

    const int base = (int)((d0 * 64u + ho) * 64u + wo);
    float* optr = out + 32ull * u;                 // 128B-aligned

    // Batch 1: windows 0..3 -> outputs 0..7, store immediately (limits regs).
    {
        const int i0 = __float_as_int(fa0), i1 = __float_as_int(fa1);
        const int i2 = __float_as_int(fa2), i3 = __float_as_int(fa3);
        const float c0 = pa0 * g, c1 = pa1 * g, c2 = pa2 * g, c3 = pa3 * g;
        float o0 = (i0 == base + 0) ? c0 : 0.0f;
        float o1 = (i0 == base + 1) ? c0 : 0.0f;
        float o2 = (i1 == base + 2) ? c1 : 0.0f;
        float o3 = (i1 == base + 3) ? c1 : 0.0f;
        float o4 = (i2 == base + 4) ? c2 : 0.0f;
        float o5 = (i2 == base + 5) ? c2 : 0.0f;
        float o6 = (i3 == base + 6) ? c3 : 0.0f;
        float o7 = (i3 == base + 7) ? c3 : 0.0f;
        asm volatile("st.global.v8.f32 [%0], {%1,%2,%3,%4,%5,%6,%7,%8};"
                     :: "l"(optr), "f"(o0), "f"(o1), "f"(o2), "f"(o3),
                        "f"(o4), "f"(o5), "f"(o6), "f"(o7) : "memory");
    }
    // Batch 2: windows 4..7 -> outputs 8..15.
    {
        const int i0 = __float_as_int(fa4), i1 = __float_as_int(fa5);
        const int i2 = __float_as_int(fa6), i3 = __float_as_int(fa7);
        const float c0 = pa4 * g, c1 = pa5 * g, c2 = pa6 * g, c3 = pa7 * g;
        float o0 = (i0 == base +  8) ? c0 : 0.0f;
        float o1 = (i0 == base +  9) ? c0 : 0.0f;
        float o2 = (i1 == base + 10) ? c1 : 0.0f;
        float o3 = (i1 == base + 11) ? c1 : 0.0f;
        float o4 = (i2 == base + 12) ? c2 : 0.0f;
        float o5 = (i2 == base + 13) ? c2 : 0.0f;
        float o6 = (i3 == base + 14) ? c3 : 0.0f;
        float o7 = (i3 == base + 15) ? c3 : 0.0f;
        asm volatile("st.global.v8.f32 [%0], {%1,%2,%3,%4,%5,%6,%7,%8};"
                     :: "l"(optr + 8), "f"(o0), "f"(o1), "f"(o2), "f"(o3),
                        "f"(o4), "f"(o5), "f"(o6), "f"(o7) : "memory");
    }
    // Batch 3: windows 8..11 -> outputs 16..23.
    {
        const int i0 = __float_as_int(fb0), i1 = __float_as_int(fb1);
        const int i2 = __float_as_int(fb2), i3 = __float_as_int(fb3);
        const float c0 = pb0 * g, c1 = pb1 * g, c2 = pb2 * g, c3 = pb3 * g;
        float o0 = (i0 == base + 16) ? c0 : 0.0f;
        float o1 = (i0 == base + 17) ? c0 : 0.0f;
        float o2 = (i1 == base + 18) ? c1 : 0.0f;
        float o3 = (i1 == base + 19) ? c1 : 0.0f;
        float o4 = (i2 == base + 20) ? c2 : 0.0f;
        float o5 = (i2 == base + 21) ? c2 : 0.0f;
        float o6 = (i3 == base + 22) ? c3 : 0.0f;
        float o7 = (i3 == base + 23) ? c3 : 0.0f;
        asm volatile("st.global.v8.f32 [%0], {%1,%2,%3,%4,%5,%6,%7,%8};"
                     :: "l"(optr + 16), "f"(o0), "f"(o1), "f"(o2), "f"(o3),
                        "f"(o4), "f"(o5), "f"(o6), "f"(o7) : "memory");
    }
    // Batch 4: windows 12..15 -> outputs 24..31.
    {
        const int i0 = __float_as_int(fb4), i1 = __float_as_int(fb5);
        const int i2 = __float_as_int(fb6), i3 = __float_as_int(fb7);
        const float c0 = pb4 * g, c1 = pb5 * g, c2 = pb6 * g, c3 = pb7 * g;
        float o0 = (i0 == base + 24) ? c0 : 0.0f;
        float o1 = (i0 == base + 25) ? c0 : 0.0f;
        float o2 = (i1 == base + 26) ? c1 : 0.0f;
        float o3 = (i1 == base + 27) ? c1 : 0.0f;
        float o4 = (i2 == base + 28) ? c2 : 0.0f;
        float o5 = (i2 == base + 29) ? c2 : 0.0f;
        float o6 = (i3 == base + 30) ? c3 : 0.0f;
        float o7 = (i3 == base + 31) ? c3 : 0.0f;
        asm volatile("st.global.v8.f32 [%0], {%1,%2,%3,%4,%5,%6,%7,%8};"
                     :: "l"(optr + 24), "f"(o0), "f"(o1), "f"(o2), "f"(o3),
                        "f"(o4), "f"(o5), "f"(o6), "f"(o7) : "memory");
    }
}

// ---------------------------------------------------------------------------
extern "C" void kernel_launch(void* const* d_in, const int* in_sizes, int n_in,
                              void* d_out, int out_size) {
    const float* pooled  = (const float*)d_in[0];
    const int*   indices = (const int*)d_in[1];
    float*       out     = (float*)d_out;

    gating_partial<<<NCHAN * SLOTS, 256>>>(pooled);          // 2048 blocks

    // PSS secondary (proven structure). 8192 blocks x 256 thr x 32 outputs.
    cudaLaunchConfig_t cfg = {};
    cfg.gridDim  = dim3(8192, 1, 1);
    cfg.blockDim = dim3(256, 1, 1);
    cfg.dynamicSmemBytes = 0;
    cfg.stream = 0;
    cudaLaunchAttribute attr[1];
    attr[0].id = cudaLaunchAttributeProgrammaticStreamSerialization;
    attr[0].val.programmaticStreamSerializationAllowed = 1;
    cfg.attrs = attr;
    cfg.numAttrs = 1;
    cudaLaunchKernelEx(&cfg, unpool_kernel, pooled, indices, out);
}

// round 16
// speedup vs baseline: 1.3072x; 1.3072x over previous
#include <cuda_runtime.h>
#include <cstdint>

// Fixed shapes: pooled/indices [4,64,32,32,32], out [4,64,64,64,64]
#define NCHAN 256
#define POOL_PER_CHAN 32768
#define SLOTS 8
#define S_TOTAL 262144.0f

__device__ float d_partial[NCHAN * SLOTS];

// ---------------------------------------------------------------------------
// Kernel 1 (primary): partial sum(silu(pooled)), 2048 blocks x 256 thr.
// Two 256-bit loads per thread, front-batched. PLC trigger at entry.
// (Byte-identical to the proven 59.5us version.)
// ---------------------------------------------------------------------------
__global__ __launch_bounds__(256) void gating_partial(const float* __restrict__ pooled) {
    cudaTriggerProgrammaticLaunchCompletion();

    const float* p = pooled + (size_t)blockIdx.x * 4096 + threadIdx.x * 8;

    float v0, v1, v2, v3, v4, v5, v6, v7;
    float w0, w1, w2, w3, w4, w5, w6, w7;
    asm volatile("ld.global.nc.v8.f32 {%0,%1,%2,%3,%4,%5,%6,%7}, [%8];"
                 : "=f"(v0), "=f"(v1), "=f"(v2), "=f"(v3),
                   "=f"(v4), "=f"(v5), "=f"(v6), "=f"(v7)
                 : "l"(p));
    asm volatile("ld.global.nc.v8.f32 {%0,%1,%2,%3,%4,%5,%6,%7}, [%8];"
                 : "=f"(w0), "=f"(w1), "=f"(w2), "=f"(w3),
                   "=f"(w4), "=f"(w5), "=f"(w6), "=f"(w7)
                 : "l"(p + 2048));

    float s = 0.0f;
    s += v0 * (1.0f / (1.0f + __expf(-v0)));
    s += v1 * (1.0f / (1.0f + __expf(-v1)));
    s += v2 * (1.0f / (1.0f + __expf(-v2)));
    s += v3 * (1.0f / (1.0f + __expf(-v3)));
    s += v4 * (1.0f / (1.0f + __expf(-v4)));
    s += v5 * (1.0f / (1.0f + __expf(-v5)));
    s += v6 * (1.0f / (1.0f + __expf(-v6)));
    s += v7 * (1.0f / (1.0f + __expf(-v7)));
    s += w0 * (1.0f / (1.0f + __expf(-w0)));
    s += w1 * (1.0f / (1.0f + __expf(-w1)));
    s += w2 * (1.0f / (1.0f + __expf(-w2)));
    s += w3 * (1.0f / (1.0f + __expf(-w3)));
    s += w4 * (1.0f / (1.0f + __expf(-w4)));
    s += w5 * (1.0f / (1.0f + __expf(-w5)));
    s += w6 * (1.0f / (1.0f + __expf(-w6)));
    s += w7 * (1.0f / (1.0f + __expf(-w7)));

    #pragma unroll
    for (int off = 16; off > 0; off >>= 1)
        s += __shfl_xor_sync(0xFFFFFFFFu, s, off);

    __shared__ float sh[8];
    const int lane = threadIdx.x & 31;
    const int wid  = threadIdx.x >> 5;
    if (lane == 0) sh[wid] = s;
    __syncthreads();
    if (threadIdx.x == 0) {
        float t = sh[0];
        #pragma unroll
        for (int j = 1; j < 8; j++) t += sh[j];
        d_partial[blockIdx.x] = t;     // slot = bc*8 + sub (fixed, deterministic)
    }
}

// ---------------------------------------------------------------------------
// Kernel 2 (PSS secondary): dense unpool + gate. 16 outputs/thread split into
// TWO warp-coalesced 8-output groups (lane stride 32B => every st.v8 covers
// a fully-written contiguous 1KB per warp; no partial-line store wavefronts).
// Group v = blk*512 + tid (+256): layout [bc(8)|d0(6)|ho(6)|wo8(3)]; both
// groups share bc/d0 (uniform per block).
// ---------------------------------------------------------------------------
__global__ __launch_bounds__(256) void unpool_kernel(const float* __restrict__ pooled,
                                                     const int*   __restrict__ indices,
                                                     float*       __restrict__ out) {
    const unsigned bc  = blockIdx.x >> 6;          // 64 blocks per channel
    const unsigned d0  = blockIdx.x & 63u;         // uniform per block
    const unsigned tid = threadIdx.x;

    const unsigned wo  = (tid & 7u) << 3;          // 0..56, step 8
    const unsigned ho0 = tid >> 3;                 // 0..31
    // group1: ho1 = ho0 + 32 (32..63)

    const unsigned pb0 = bc * POOL_PER_CHAN + (d0 >> 1) * 1024u
                       + (ho0 >> 1) * 32u + (wo >> 1);
    const unsigned pb1 = pb0 + 512u;               // (ho1>>1)-(ho0>>1) = 16 rows

    // Front-issue all four loads (MLP=4, independent of the gating grid).
    const int4   ia = __ldg(reinterpret_cast<const int4*>(indices + pb0));
    const int4   ib = __ldg(reinterpret_cast<const int4*>(indices + pb1));
    const float4 pa = __ldg(reinterpret_cast<const float4*>(pooled + pb0));
    const float4 pb = __ldg(reinterpret_cast<const float4*>(pooled + pb1));

    // Wait for gating grid completion (PDL dependency point).
    cudaGridDependencySynchronize();

    __shared__ float gsh;
    if (tid == 0) {
        const float* pp = d_partial + bc * SLOTS;
        float t = 0.0f;
        #pragma unroll
        for (int j = 0; j < SLOTS; j++) t += pp[j];   // fixed order: deterministic
        float m = t / S_TOTAL;
        gsh = fminf(m, 0.0f) - log1pf(__expf(-fabsf(m)));   // log_sigmoid(m)
    }
    __syncthreads();
    const float g = gsh;

    const int base0 = (int)((d0 * 64u + ho0) * 64u + wo);
    const int base1 = base0 + 2048;                // ho + 32 => +32*64

    float* optr = out + 8ull * (blockIdx.x * 512u + tid);   // 32B-aligned

    // Group 0 (ho0): outputs base0 .. base0+7.
    {
        const float c0 = pa.x * g, c1 = pa.y * g, c2 = pa.z * g, c3 = pa.w * g;
        float o0 = (ia.x == base0 + 0) ? c0 : 0.0f;
        float o1 = (ia.x == base0 + 1) ? c0 : 0.0f;
        float o2 = (ia.y == base0 + 2) ? c1 : 0.0f;
        float o3 = (ia.y == base0 + 3) ? c1 : 0.0f;
        float o4 = (ia.z == base0 + 4) ? c2 : 0.0f;
        float o5 = (ia.z == base0 + 5) ? c2 : 0.0f;
        float o6 = (ia.w == base0 + 6) ? c3 : 0.0f;
        float o7 = (ia.w == base0 + 7) ? c3 : 0.0f;
        asm volatile("st.global.v8.f32 [%0], {%1,%2,%3,%4,%5,%6,%7,%8};"
                     :: "l"(optr), "f"(o0), "f"(o1), "f"(o2), "f"(o3),
                        "f"(o4), "f"(o5), "f"(o6), "f"(o7) : "memory");
    }
    // Group 1 (ho1 = ho0+32): outputs base1 .. base1+7, stored 2048 floats on.
    {
        const float c0 = pb.x * g, c1 = pb.y * g, c2 = pb.z * g, c3 = pb.w * g;
        float o0 = (ib.x == base1 + 0) ? c0 : 0.0f;
        float o1 = (ib.x == base1 + 1) ? c0 : 0.0f;
        float o2 = (ib.y == base1 + 2) ? c1 : 0.0f;
        float o3 = (ib.y == base1 + 3) ? c1 : 0.0f;
        float o4 = (ib.z == base1 + 4) ? c2 : 0.0f;
        float o5 = (ib.z == base1 + 5) ? c2 : 0.0f;
        float o6 = (ib.w == base1 + 6) ? c3 : 0.0f;
        float o7 = (ib.w == base1 + 7) ? c3 : 0.0f;
        asm volatile("st.global.v8.f32 [%0], {%1,%2,%3,%4,%5,%6,%7,%8};"
                     :: "l"(optr + 2048), "f"(o0), "f"(o1), "f"(o2), "f"(o3),
                        "f"(o4), "f"(o5), "f"(o6), "f"(o7) : "memory");
    }
}

// ---------------------------------------------------------------------------
extern "C" void kernel_launch(void* const* d_in, const int* in_sizes, int n_in,
                              void* d_out, int out_size) {
    const float* pooled  = (const float*)d_in[0];
    const int*   indices = (const int*)d_in[1];
    float*       out     = (float*)d_out;

    gating_partial<<<NCHAN * SLOTS, 256>>>(pooled);          // 2048 blocks

    // PSS secondary (proven structure). 16384 blocks x 256 thr x 16 outputs.
    cudaLaunchConfig_t cfg = {};
    cfg.gridDim  = dim3(16384, 1, 1);
    cfg.blockDim = dim3(256, 1, 1);
    cfg.dynamicSmemBytes = 0;
    cfg.stream = 0;
    cudaLaunchAttribute attr[1];
    attr[0].id = cudaLaunchAttributeProgrammaticStreamSerialization;
    attr[0].val.programmaticStreamSerializationAllowed = 1;
    cfg.attrs = attr;
    cfg.numAttrs = 1;
    cudaLaunchKernelEx(&cfg, unpool_kernel, pooled, indices, out);
}